// round 6
// baseline (speedup 1.0000x reference)
#include <cuda_runtime.h>
#include <cuda_fp16.h>
#include <cstdint>

#define IN_DIM   4096
#define OUT_DIM  16384
#define MDIM     32

#define NTILE    64             // output cols per CTA
#define KC       64             // K per chunk (64 halves = 128B rows, SW128)
#define NCHUNK   (IN_DIM / KC)  // 64
#define K_PER_MMA 16            // fp16: 32B per MMA step
#define MMA_M    128
#define MMA_IDESC ((1u<<4) | ((NTILE/8)<<17) | ((MMA_M/16)<<24))   // f32 acc, f16 in

// ---- dynamic smem layout (bytes)
#define SM_TMEMPTR 0
#define SM_MBAR0   8
#define SM_MBAR1   16
#define SM_A0      1024
#define SM_A1      (SM_A0 + 16384)
#define SM_B0      (SM_A1 + 16384)
#define SM_B1      (SM_B0 + 8192)
#define SMEM_TOTAL (SM_B1 + 8192)           // 50176 B -> 2 CTAs/SM
// epilogue scratch reuses the A0 region after MMA drain
#define EP_OFF     SM_A0                    // [32][33] floats
#define YS_OFF     (SM_A0 + 4352)           // [32][68] floats

// arch-specific gate: tcgen05 only exists in the sm_103a-specific target.
// The harness also runs a plain compute_103 ptxas pass which must never see it.
#if defined(__CUDA_ARCH_FEAT_SM103_ALL) || defined(__CUDA_ARCH_FEAT_SM100_ALL) || \
    defined(__CUDA_ARCH_FEAT_SM101_ALL) || \
    (defined(__CUDA_ARCH_SPECIFIC__)) || (defined(__CUDA_ARCH_FAMILY_SPECIFIC__))
#define TC_OK 1
#else
#define TC_OK 0
#endif

// pre-converted A: rows 0..31 = hi(x), rows 32..63 = lo(x), fp16, row-major [64][4096]
__device__ __half g_A[64 * IN_DIM];

#define SW128(o) ((o) ^ (((o) >> 3) & 0x70))

#if TC_OK
__device__ __forceinline__ uint32_t elect1() {
    uint32_t p;
    asm volatile("{\n\t.reg .pred p;\n\telect.sync _|p, 0xFFFFFFFF;\n\tselp.b32 %0, 1, 0, p;\n\t}" : "=r"(p));
    return p;
}

__device__ __forceinline__ void mma_f16_ss(uint32_t d_tmem, uint64_t a_desc,
                                           uint64_t b_desc, uint32_t idesc, uint32_t en) {
    asm volatile(
        "{\n\t.reg .pred p;\n\tsetp.ne.u32 p, %4, 0;\n\t"
        "tcgen05.mma.cta_group::1.kind::f16 [%0], %1, %2, %3, {%5, %5, %5, %5}, p;\n\t}"
        :: "r"(d_tmem), "l"(a_desc), "l"(b_desc), "r"(idesc), "r"(en), "r"(0u)
        : "memory");
}

// K-major SW128 smem descriptor (LBO=1, SBO=64, version=1, layout=SW128)
__device__ __forceinline__ uint64_t mk_desc(uint32_t saddr) {
    return ((uint64_t)2 << 61) | ((uint64_t)1 << 46) | ((uint64_t)64 << 32)
         | ((uint64_t)1 << 16) | ((uint64_t)(saddr >> 4) & 0x3FFF);
}

__device__ __forceinline__ void mbar_wait(uint32_t mb, int phase) {
    uint32_t done;
    asm volatile(
        "{\n\t.reg .pred p;\n\t"
        "mbarrier.try_wait.parity.acquire.cta.shared::cta.b64 p, [%1], %2;\n\t"
        "selp.b32 %0, 1, 0, p;\n\t}" : "=r"(done) : "r"(mb), "r"(phase) : "memory");
    if (!done) {
        asm volatile(
            "{\n\t.reg .pred P1;\n\tW0_%=:\n\t"
            "mbarrier.try_wait.parity.acquire.cta.shared::cta.b64 P1, [%0], %1, 0x989680;\n\t"
            "@P1 bra.uni W1_%=;\n\tbra.uni W0_%=;\n\tW1_%=:\n\t}"
            :: "r"(mb), "r"(phase) : "memory");
    }
}
#endif

__global__ void xsplit_kernel(const float* __restrict__ x) {
    int i = blockIdx.x * blockDim.x + threadIdx.x;   // 0 .. 32*4096-1
    if (i >= MDIM * IN_DIM) return;
    float v  = x[i];
    __half h = __float2half_rn(v);
    __half l = __float2half_rn(v - __half2float(h));
    int m = i / IN_DIM, k = i % IN_DIM;
    g_A[m * IN_DIM + k]        = h;
    g_A[(m + 32) * IN_DIM + k] = l;
}

__global__ __launch_bounds__(256, 2)
void qgemm_tc(const int* __restrict__ wq,
              const int* __restrict__ zerop,
              const float* __restrict__ scalep,
              const float* __restrict__ bias,
              float* __restrict__ out)
{
#if TC_OK
    extern __shared__ char smem[];
    const uint32_t sb = (uint32_t)__cvta_generic_to_shared(smem);
    const int t   = threadIdx.x;
    const int wid = t >> 5;
    const int lid = t & 31;
    const int o0  = blockIdx.x * NTILE;

    // half2 constant: -(1024 + zero) in both lanes
    const int zero = zerop[0];
    const __half  hz  = __int2half_rn(-1024 - zero);
    const __half2 hz2 = __halves2half2(hz, hz);

    // ---- init: TMEM alloc, mbarriers, zero A pad rows (64..127 of both A bufs)
    if (wid == 0) {
        asm volatile("tcgen05.alloc.cta_group::1.sync.aligned.shared::cta.b32 [%0], %1;"
                     :: "r"(sb + SM_TMEMPTR), "r"(64u) : "memory");
    }
    if (t == 0) {
        asm volatile("mbarrier.init.shared.b64 [%0], 1;" :: "r"(sb + SM_MBAR0) : "memory");
        asm volatile("mbarrier.init.shared.b64 [%0], 1;" :: "r"(sb + SM_MBAR1) : "memory");
    }
    {
        uint4 z = make_uint4(0, 0, 0, 0);
        for (int i = t; i < 512; i += 256) {           // 512 * 16B = 8KB per buffer
            *(uint4*)(smem + SM_A0 + 8192 + i * 16) = z;
            *(uint4*)(smem + SM_A1 + 8192 + i * 16) = z;
        }
    }
    __syncthreads();
    uint32_t tmem;
    asm volatile("ld.shared.b32 %0, [%1];" : "=r"(tmem) : "r"(sb + SM_TMEMPTR));

    // ---- load maps
    // B: row r = t>>2 (0..63), q = t&3; 16 consecutive ints (64B) per thread
    const int br = t >> 2, bq = t & 3;
    const int* bbase = wq + (size_t)(o0 + br) * IN_DIM + bq * 16;
    // A: row ar = t>>2 (0..63), as = t&3 (32B); 2 int4 LDG from fp16 g_A
    const int ar = t >> 2, as = t & 3;
    const char* abase = (const char*)g_A + ((size_t)ar * IN_DIM) * 2 + as * 32;

    int4 qreg[2][4];
    int4 areg[2][2];

#define LDGC(set, c)                                                              \
    do {                                                                          \
        _Pragma("unroll")                                                         \
        for (int j = 0; j < 4; j++)                                               \
            qreg[set][j] = *(const int4*)(bbase + (c) * KC + j * 4);              \
        areg[set][0] = *(const int4*)(abase + (c) * (KC * 2));                    \
        areg[set][1] = *(const int4*)(abase + (c) * (KC * 2) + 16);               \
    } while (0)

#define STSC(set, buf)                                                            \
    do {                                                                          \
        const uint32_t bB = sb + ((buf) ? SM_B1 : SM_B0);                         \
        _Pragma("unroll")                                                         \
        for (int p = 0; p < 2; p++) {                                             \
            int4 qa = qreg[set][2 * p], qb = qreg[set][2 * p + 1];                 \
            uint32_t u0 = ((uint32_t)qa.x | ((uint32_t)qa.y << 16)) + 0x64006400u;\
            uint32_t u1 = ((uint32_t)qa.z | ((uint32_t)qa.w << 16)) + 0x64006400u;\
            uint32_t u2 = ((uint32_t)qb.x | ((uint32_t)qb.y << 16)) + 0x64006400u;\
            uint32_t u3 = ((uint32_t)qb.z | ((uint32_t)qb.w << 16)) + 0x64006400u;\
            __half2 h0 = __hadd2(*(__half2*)&u0, hz2);                            \
            __half2 h1 = __hadd2(*(__half2*)&u1, hz2);                            \
            __half2 h2 = __hadd2(*(__half2*)&u2, hz2);                            \
            __half2 h3 = __hadd2(*(__half2*)&u3, hz2);                            \
            uint32_t off = SW128((uint32_t)(br * 128 + bq * 32 + p * 16));        \
            asm volatile("st.shared.v4.b32 [%0], {%1, %2, %3, %4};"               \
                :: "r"(bB + off), "r"(*(uint32_t*)&h0), "r"(*(uint32_t*)&h1),     \
                   "r"(*(uint32_t*)&h2), "r"(*(uint32_t*)&h3) : "memory");        \
        }                                                                         \
        const uint32_t bA = sb + ((buf) ? SM_A1 : SM_A0);                         \
        _Pragma("unroll")                                                         \
        for (int j = 0; j < 2; j++) {                                             \
            uint32_t off = SW128((uint32_t)(ar * 128 + as * 32 + j * 16));        \
            int4 v = areg[set][j];                                                \
            asm volatile("st.shared.v4.b32 [%0], {%1, %2, %3, %4};"               \
                :: "r"(bA + off), "r"(v.x), "r"(v.y), "r"(v.z), "r"(v.w) : "memory"); \
        }                                                                         \
    } while (0)

    int ph[2] = {0, 0};

    LDGC(0, 0);

    for (int c = 0; c < NCHUNK; c++) {
        const int buf = c & 1, set = c & 1;

        // issue next chunk's LDG FIRST: overlaps DRAM fetch with the mbar wait
        if (c + 1 < NCHUNK) LDGC(set ^ 1, c + 1);

        // wait for the MMA (issued at chunk c-2) that reads buffer `buf`
        if (c >= 2) {
            mbar_wait(sb + (buf ? SM_MBAR1 : SM_MBAR0), ph[buf]);
            ph[buf] ^= 1;
        }

        STSC(set, buf);

        asm volatile("fence.proxy.async.shared::cta;" ::: "memory");
        __syncthreads();

        if (wid == 0 && elect1()) {
            uint64_t ad = mk_desc(sb + (buf ? SM_A1 : SM_A0));
            uint64_t bd = mk_desc(sb + (buf ? SM_B1 : SM_B0));
#pragma unroll
            for (int s = 0; s < KC / K_PER_MMA; s++)
                mma_f16_ss(tmem, ad + s * 2, bd + s * 2, MMA_IDESC,
                           (c > 0 || s > 0) ? 1u : 0u);
            asm volatile(
                "tcgen05.commit.cta_group::1.mbarrier::arrive::one.shared::cluster.b64 [%0];"
                :: "r"(sb + (buf ? SM_MBAR1 : SM_MBAR0)) : "memory");
        }
    }

    // ---- drain both buffers
#pragma unroll
    for (int b = 0; b < 2; b++)
        mbar_wait(sb + (b ? SM_MBAR1 : SM_MBAR0), ph[b]);
    asm volatile("tcgen05.fence::after_thread_sync;" ::: "memory");
    __syncthreads();   // A0 region about to be reused as epilogue scratch

    // ---- epilogue: warp0 holds hi rows (m=lid), warp1 holds lo rows
    const float scale = scalep[0];
    float* Ep = (float*)(smem + EP_OFF);     // [32][33]
    float* Ys = (float*)(smem + YS_OFF);     // [32][68]

    for (int s = 0; s < 2; s++) {
        uint32_t d[32];
        if (wid < 2) {
            asm volatile(
                "tcgen05.ld.sync.aligned.32x32b.x32.b32 "
                "{%0,%1,%2,%3,%4,%5,%6,%7,%8,%9,%10,%11,%12,%13,%14,%15,"
                "%16,%17,%18,%19,%20,%21,%22,%23,%24,%25,%26,%27,%28,%29,%30,%31}, [%32];"
                : "=r"(d[0]), "=r"(d[1]), "=r"(d[2]), "=r"(d[3]), "=r"(d[4]), "=r"(d[5]),
                  "=r"(d[6]), "=r"(d[7]), "=r"(d[8]), "=r"(d[9]), "=r"(d[10]), "=r"(d[11]),
                  "=r"(d[12]), "=r"(d[13]), "=r"(d[14]), "=r"(d[15]), "=r"(d[16]), "=r"(d[17]),
                  "=r"(d[18]), "=r"(d[19]), "=r"(d[20]), "=r"(d[21]), "=r"(d[22]), "=r"(d[23]),
                  "=r"(d[24]), "=r"(d[25]), "=r"(d[26]), "=r"(d[27]), "=r"(d[28]), "=r"(d[29]),
                  "=r"(d[30]), "=r"(d[31])
                : "r"(tmem + s * 32));
            asm volatile("tcgen05.wait::ld.sync.aligned;" ::: "memory");
        }
        if (wid == 1) {
#pragma unroll
            for (int cc = 0; cc < 32; cc++) Ep[lid * 33 + cc] = __uint_as_float(d[cc]);
        }
        __syncthreads();
        if (wid == 0) {
#pragma unroll
            for (int cc = 0; cc < 32; cc++) {
                float hi = __uint_as_float(d[cc]);
                float lo = Ep[lid * 33 + cc];
                float b  = bias[o0 + s * 32 + cc];
                Ys[lid * 68 + s * 32 + cc] = fmaf(scale, hi + lo, b);
            }
        }
        __syncthreads();
    }

    // ---- coalesced store: 32 rows x 64 cols
    {
        const int m = t >> 3, q8 = t & 7;
#pragma unroll
        for (int i = 0; i < 2; i++) {
            const int q = q8 + 8 * i;                 // float4 index 0..15
            float4 v = *(const float4*)(Ys + m * 68 + q * 4);
            *(float4*)(out + (size_t)m * OUT_DIM + o0 + q * 4) = v;
        }
    }

    __syncthreads();
    if (t == 0) {
        asm volatile("mbarrier.inval.shared.b64 [%0];" :: "r"(sb + SM_MBAR0) : "memory");
        asm volatile("mbarrier.inval.shared.b64 [%0];" :: "r"(sb + SM_MBAR1) : "memory");
    }
    __syncthreads();
    if (wid == 0) {
        asm volatile("tcgen05.dealloc.cta_group::1.sync.aligned.b32 %0, %1;"
                     :: "r"(tmem), "r"(64u));
    }
#endif  // TC_OK
}

extern "C" void kernel_launch(void* const* d_in, const int* in_sizes, int n_in,
                              void* d_out, int out_size)
{
    const float* x     = (const float*)d_in[0];
    const int*   wq    = (const int*)  d_in[1];
    const int*   zero  = (const int*)  d_in[2];
    const float* scale = (const float*)d_in[3];
    const float* bias  = (const float*)d_in[4];
    float*       out   = (float*)d_out;

    cudaFuncSetAttribute(qgemm_tc, cudaFuncAttributeMaxDynamicSharedMemorySize, SMEM_TOTAL);

    xsplit_kernel<<<(MDIM * IN_DIM + 255) / 256, 256>>>(x);
    qgemm_tc<<<OUT_DIM / NTILE, 256, SMEM_TOTAL>>>(wq, zero, scale, bias, out);
}

// round 7
// speedup vs baseline: 1.7774x; 1.7774x over previous
#include <cuda_runtime.h>
#include <cuda_fp16.h>
#include <cstdint>

#define IN_DIM   4096
#define OUT_DIM  16384
#define MDIM     32

#define NTILE    128            // output cols per CTA
#define KC       64             // K per chunk (64 halves = 128B rows, SW128)
#define NCHUNK   (IN_DIM / KC)  // 64
#define NSTAGE   4
#define K_PER_MMA 16            // fp16: 32B per MMA step
#define MMA_M    128
#define MMA_IDESC ((1u<<4) | ((NTILE/8)<<17) | ((MMA_M/16)<<24))   // f32 acc, f16 in

// ---- dynamic smem layout (bytes)
#define SM_TMEMPTR 0
#define SM_MBAR(s) (8 + 8*(s))
#define SM_A(s)    (1024 + (s)*16384)            // 4 x 16KB (rows 64..127 zero pad)
#define SM_B(s)    (66560 + (s)*16384)           // 4 x 16KB
#define SMEM_TOTAL 132096
// epilogue scratch reuses stage-0 A after drain
#define EP_OFF     1024                          // [32][33] floats
#define YS_OFF     (1024 + 4352)                 // [32][132] floats

// arch-specific gate: tcgen05 only exists in the sm_103a-specific target.
// The harness also runs a plain compute_103 ptxas pass which must never see it.
#if defined(__CUDA_ARCH_FEAT_SM103_ALL) || defined(__CUDA_ARCH_FEAT_SM100_ALL) || \
    defined(__CUDA_ARCH_FEAT_SM101_ALL) || \
    (defined(__CUDA_ARCH_SPECIFIC__)) || (defined(__CUDA_ARCH_FAMILY_SPECIFIC__))
#define TC_OK 1
#else
#define TC_OK 0
#endif

// pre-converted A: rows 0..31 = hi(x), rows 32..63 = lo(x), fp16, row-major [64][4096]
__device__ __half g_A[64 * IN_DIM];

#define SW128(o) ((o) ^ (((o) >> 3) & 0x70))

#if TC_OK
__device__ __forceinline__ uint32_t elect1() {
    uint32_t p;
    asm volatile("{\n\t.reg .pred p;\n\telect.sync _|p, 0xFFFFFFFF;\n\tselp.b32 %0, 1, 0, p;\n\t}" : "=r"(p));
    return p;
}

__device__ __forceinline__ void mma_f16_ss(uint32_t d_tmem, uint64_t a_desc,
                                           uint64_t b_desc, uint32_t idesc, uint32_t en) {
    asm volatile(
        "{\n\t.reg .pred p;\n\tsetp.ne.u32 p, %4, 0;\n\t"
        "tcgen05.mma.cta_group::1.kind::f16 [%0], %1, %2, %3, {%5, %5, %5, %5}, p;\n\t}"
        :: "r"(d_tmem), "l"(a_desc), "l"(b_desc), "r"(idesc), "r"(en), "r"(0u)
        : "memory");
}

// K-major SW128 smem descriptor (LBO=1, SBO=64, version=1, layout=SW128)
__device__ __forceinline__ uint64_t mk_desc(uint32_t saddr) {
    return ((uint64_t)2 << 61) | ((uint64_t)1 << 46) | ((uint64_t)64 << 32)
         | ((uint64_t)1 << 16) | ((uint64_t)(saddr >> 4) & 0x3FFF);
}

__device__ __forceinline__ void mbar_wait(uint32_t mb, int phase) {
    uint32_t done;
    asm volatile(
        "{\n\t.reg .pred p;\n\t"
        "mbarrier.try_wait.parity.acquire.cta.shared::cta.b64 p, [%1], %2;\n\t"
        "selp.b32 %0, 1, 0, p;\n\t}" : "=r"(done) : "r"(mb), "r"(phase) : "memory");
    if (!done) {
        asm volatile(
            "{\n\t.reg .pred P1;\n\tW0_%=:\n\t"
            "mbarrier.try_wait.parity.acquire.cta.shared::cta.b64 P1, [%0], %1, 0x989680;\n\t"
            "@P1 bra.uni W1_%=;\n\tbra.uni W0_%=;\n\tW1_%=:\n\t}"
            :: "r"(mb), "r"(phase) : "memory");
    }
}

__device__ __forceinline__ void cp16(uint32_t dst, const void* src) {
    asm volatile("cp.async.ca.shared.global [%0], [%1], 16;"
                 :: "r"(dst), "l"(src) : "memory");
}
#endif

__global__ void xsplit_kernel(const float* __restrict__ x) {
    int i = blockIdx.x * blockDim.x + threadIdx.x;   // 0 .. 32*4096-1
    if (i >= MDIM * IN_DIM) return;
    float v  = x[i];
    __half h = __float2half_rn(v);
    __half l = __float2half_rn(v - __half2float(h));
    int m = i / IN_DIM, k = i % IN_DIM;
    g_A[m * IN_DIM + k]        = h;
    g_A[(m + 32) * IN_DIM + k] = l;
}

__global__ __launch_bounds__(256, 1)
void qgemm_tc(const int* __restrict__ wq,
              const int* __restrict__ zerop,
              const float* __restrict__ scalep,
              const float* __restrict__ bias,
              float* __restrict__ out)
{
#if TC_OK
    extern __shared__ char smem[];
    const uint32_t sb = (uint32_t)__cvta_generic_to_shared(smem);
    const int t   = threadIdx.x;
    const int wid = t >> 5;
    const int lid = t & 31;
    const int o0  = blockIdx.x * NTILE;

    // half2 constant: -(1024 + zero) in both lanes
    const int zero = zerop[0];
    const __half  hz  = __int2half_rn(-1024 - zero);
    const __half2 hz2 = __halves2half2(hz, hz);

    if (wid == 0) {
        asm volatile("tcgen05.alloc.cta_group::1.sync.aligned.shared::cta.b32 [%0], %1;"
                     :: "r"(sb + SM_TMEMPTR), "r"(128u) : "memory");
    }
    if (t == 0) {
#pragma unroll
        for (int s = 0; s < NSTAGE; s++)
            asm volatile("mbarrier.init.shared.b64 [%0], 1;" :: "r"(sb + SM_MBAR(s)) : "memory");
    }
    // zero A pad rows (bytes 8192..16384 of each A stage)
    {
        uint4 z = make_uint4(0, 0, 0, 0);
#pragma unroll
        for (int s = 0; s < NSTAGE; s++)
            for (int i = t; i < 512; i += 256)
                *(uint4*)(smem + SM_A(s) + 8192 + i * 16) = z;
    }
    __syncthreads();
    uint32_t tmem;
    asm volatile("ld.shared.b32 %0, [%1];" : "=r"(tmem) : "r"(sb + SM_TMEMPTR));

    // ---- load maps
    // B: row br = t>>1 (0..127), half bh = t&1 (k range [32bh, 32bh+32)); 8 int4 LDG
    const int br = t >> 1, bh = t & 1;
    const int* bbase = wq + (size_t)(o0 + br) * IN_DIM + bh * 32;
    // A: row ar = t>>2 (0..63), seg as = t&3 (32B); 2x cp.async 16B
    const int ar = t >> 2, as = t & 3;
    const char* abase = (const char*)g_A + ((size_t)ar * IN_DIM) * 2 + as * 32;
    const uint32_t a_sw0 = SW128((uint32_t)(ar * 128 + as * 32));
    const uint32_t a_sw1 = SW128((uint32_t)(ar * 128 + as * 32 + 16));

    int4 qreg[2][8];

#define LDGC(set, c)                                                              \
    do {                                                                          \
        _Pragma("unroll")                                                         \
        for (int j = 0; j < 8; j++)                                               \
            qreg[set][j] = __ldcs((const int4*)(bbase + (c) * KC + j * 4));       \
    } while (0)

#define CPA(c)                                                                    \
    do {                                                                          \
        const uint32_t bA = sb + SM_A((c) & (NSTAGE - 1));                        \
        cp16(bA + a_sw0, abase + (c) * (KC * 2));                                 \
        cp16(bA + a_sw1, abase + (c) * (KC * 2) + 16);                            \
        asm volatile("cp.async.commit_group;" ::: "memory");                      \
    } while (0)

#define STSC(set, st)                                                             \
    do {                                                                          \
        const uint32_t bB = sb + SM_B(st);                                        \
        _Pragma("unroll")                                                         \
        for (int g = 0; g < 4; g++) {                                             \
            int4 qa = qreg[set][2 * g], qb = qreg[set][2 * g + 1];                 \
            uint32_t u0 = ((uint32_t)qa.x | ((uint32_t)qa.y << 16)) + 0x64006400u;\
            uint32_t u1 = ((uint32_t)qa.z | ((uint32_t)qa.w << 16)) + 0x64006400u;\
            uint32_t u2 = ((uint32_t)qb.x | ((uint32_t)qb.y << 16)) + 0x64006400u;\
            uint32_t u3 = ((uint32_t)qb.z | ((uint32_t)qb.w << 16)) + 0x64006400u;\
            __half2 h0 = __hadd2(*(__half2*)&u0, hz2);                            \
            __half2 h1 = __hadd2(*(__half2*)&u1, hz2);                            \
            __half2 h2 = __hadd2(*(__half2*)&u2, hz2);                            \
            __half2 h3 = __hadd2(*(__half2*)&u3, hz2);                            \
            uint32_t off = SW128((uint32_t)(br * 128 + bh * 64 + g * 16));        \
            asm volatile("st.shared.v4.b32 [%0], {%1, %2, %3, %4};"               \
                :: "r"(bB + off), "r"(*(uint32_t*)&h0), "r"(*(uint32_t*)&h1),     \
                   "r"(*(uint32_t*)&h2), "r"(*(uint32_t*)&h3) : "memory");        \
        }                                                                         \
    } while (0)

    int ph[NSTAGE] = {0, 0, 0, 0};

    LDGC(0, 0);
    CPA(0);

    for (int c = 0; c < NCHUNK; c++) {
        const int st = c & (NSTAGE - 1), set = c & 1;

        // issue next chunk's loads first: DRAM latency overlaps this chunk's work
        if (c + 1 < NCHUNK) {
            LDGC(set ^ 1, c + 1);
            CPA(c + 1);
        }

        // gate stage reuse on MMA from chunk c-NSTAGE (long done in steady state)
        if (c >= NSTAGE) {
            mbar_wait(sb + SM_MBAR(st), ph[st]);
            ph[st] ^= 1;
        }

        STSC(set, st);

        // A for chunk c must have landed (<=1 pending group = chunk c+1)
        if (c + 1 < NCHUNK)
            asm volatile("cp.async.wait_group 1;" ::: "memory");
        else
            asm volatile("cp.async.wait_group 0;" ::: "memory");

        asm volatile("fence.proxy.async.shared::cta;" ::: "memory");
        __syncthreads();

        if (wid == 0 && elect1()) {
            uint64_t ad = mk_desc(sb + SM_A(st));
            uint64_t bd = mk_desc(sb + SM_B(st));
#pragma unroll
            for (int s = 0; s < KC / K_PER_MMA; s++)
                mma_f16_ss(tmem, ad + s * 2, bd + s * 2, MMA_IDESC,
                           (c > 0 || s > 0) ? 1u : 0u);
            asm volatile(
                "tcgen05.commit.cta_group::1.mbarrier::arrive::one.shared::cluster.b64 [%0];"
                :: "r"(sb + SM_MBAR(st)) : "memory");
        }
    }

    // ---- drain all stages
#pragma unroll
    for (int s = 0; s < NSTAGE; s++)
        mbar_wait(sb + SM_MBAR(s), ph[s]);
    asm volatile("tcgen05.fence::after_thread_sync;" ::: "memory");
    __syncthreads();   // stage-0 A about to be reused as epilogue scratch

    // ---- epilogue: warp0 holds hi rows (m=lid), warp1 holds lo rows
    const float scale = scalep[0];
    float* Ep = (float*)(smem + EP_OFF);     // [32][33]
    float* Ys = (float*)(smem + YS_OFF);     // [32][132]

    for (int s = 0; s < 4; s++) {
        uint32_t d[32];
        if (wid < 2) {
            asm volatile(
                "tcgen05.ld.sync.aligned.32x32b.x32.b32 "
                "{%0,%1,%2,%3,%4,%5,%6,%7,%8,%9,%10,%11,%12,%13,%14,%15,"
                "%16,%17,%18,%19,%20,%21,%22,%23,%24,%25,%26,%27,%28,%29,%30,%31}, [%32];"
                : "=r"(d[0]), "=r"(d[1]), "=r"(d[2]), "=r"(d[3]), "=r"(d[4]), "=r"(d[5]),
                  "=r"(d[6]), "=r"(d[7]), "=r"(d[8]), "=r"(d[9]), "=r"(d[10]), "=r"(d[11]),
                  "=r"(d[12]), "=r"(d[13]), "=r"(d[14]), "=r"(d[15]), "=r"(d[16]), "=r"(d[17]),
                  "=r"(d[18]), "=r"(d[19]), "=r"(d[20]), "=r"(d[21]), "=r"(d[22]), "=r"(d[23]),
                  "=r"(d[24]), "=r"(d[25]), "=r"(d[26]), "=r"(d[27]), "=r"(d[28]), "=r"(d[29]),
                  "=r"(d[30]), "=r"(d[31])
                : "r"(tmem + s * 32));
            asm volatile("tcgen05.wait::ld.sync.aligned;" ::: "memory");
        }
        if (wid == 1) {
#pragma unroll
            for (int cc = 0; cc < 32; cc++) Ep[lid * 33 + cc] = __uint_as_float(d[cc]);
        }
        __syncthreads();
        if (wid == 0) {
#pragma unroll
            for (int cc = 0; cc < 32; cc++) {
                float hi = __uint_as_float(d[cc]);
                float lo = Ep[lid * 33 + cc];
                float b  = bias[o0 + s * 32 + cc];
                Ys[lid * 132 + s * 32 + cc] = fmaf(scale, hi + lo, b);
            }
        }
        __syncthreads();
    }

    // ---- coalesced store: 32 rows x 128 cols
    {
        const int m = t >> 3, q8 = t & 7;
#pragma unroll
        for (int i = 0; i < 4; i++) {
            const int q = q8 + 8 * i;                 // float4 index 0..31
            float4 v = *(const float4*)(Ys + m * 132 + q * 4);
            *(float4*)(out + (size_t)m * OUT_DIM + o0 + q * 4) = v;
        }
    }

    __syncthreads();
    if (t == 0) {
#pragma unroll
        for (int s = 0; s < NSTAGE; s++)
            asm volatile("mbarrier.inval.shared.b64 [%0];" :: "r"(sb + SM_MBAR(s)) : "memory");
    }
    __syncthreads();
    if (wid == 0) {
        asm volatile("tcgen05.dealloc.cta_group::1.sync.aligned.b32 %0, %1;"
                     :: "r"(tmem), "r"(128u));
    }
#endif  // TC_OK
}

extern "C" void kernel_launch(void* const* d_in, const int* in_sizes, int n_in,
                              void* d_out, int out_size)
{
    const float* x     = (const float*)d_in[0];
    const int*   wq    = (const int*)  d_in[1];
    const int*   zero  = (const int*)  d_in[2];
    const float* scale = (const float*)d_in[3];
    const float* bias  = (const float*)d_in[4];
    float*       out   = (float*)d_out;

    cudaFuncSetAttribute(qgemm_tc, cudaFuncAttributeMaxDynamicSharedMemorySize, SMEM_TOTAL);

    xsplit_kernel<<<(MDIM * IN_DIM + 255) / 256, 256>>>(x);
    qgemm_tc<<<OUT_DIM / NTILE, 256, SMEM_TOTAL>>>(wq, zero, scale, bias, out);
}

// round 8
// speedup vs baseline: 2.5941x; 1.4595x over previous
#include <cuda_runtime.h>
#include <cuda_fp16.h>
#include <cstdint>

#define IN_DIM   4096
#define OUT_DIM  16384
#define MDIM     32

#define NTILE    128            // output cols per CTA
#define KC       64             // K per chunk
#define NCHUNK   (IN_DIM / KC)  // 64
#define NSTAGE   3
#define K_PER_MMA 16            // fp16: 32B per MMA step
#define MMA_M    128
#define MMA_IDESC ((1u<<4) | ((NTILE/8)<<17) | ((MMA_M/16)<<24))   // f32 acc, f16 in

// ---- dynamic smem layout (bytes)
#define SM_TMEMPTR 0
#define SM_MBAR(s) (8 + 8*(s))
#define SM_A(s)    (1024 + (s)*16384)             // 3 x 16KB fp16 A (rows 64..127 pad)
#define SM_ST(s)   (50176 + (s)*32768)            // 3 x 32KB raw int32 B staging
#define SM_BF(s)   (148480 + (s)*16384)           // 3 x 16KB fp16 B
#define SMEM_TOTAL 197632
// epilogue scratch reuses stage-0 A region after drain
#define EP_OFF     1024                           // [32][33] floats
#define YS_OFF     (1024 + 4352)                  // [32][132] floats

// arch-specific gate: tcgen05 only exists in the sm_103a-specific target.
#if defined(__CUDA_ARCH_FEAT_SM103_ALL) || defined(__CUDA_ARCH_FEAT_SM100_ALL) || \
    defined(__CUDA_ARCH_FEAT_SM101_ALL) || \
    (defined(__CUDA_ARCH_SPECIFIC__)) || (defined(__CUDA_ARCH_FAMILY_SPECIFIC__))
#define TC_OK 1
#else
#define TC_OK 0
#endif

// pre-converted A: rows 0..31 = hi(x), rows 32..63 = lo(x), fp16, row-major [64][4096]
__device__ __align__(1024) __half g_A[64 * IN_DIM];

#define SW128(o) ((o) ^ (((o) >> 3) & 0x70))

#if TC_OK
__device__ __forceinline__ uint32_t elect1() {
    uint32_t p;
    asm volatile("{\n\t.reg .pred p;\n\telect.sync _|p, 0xFFFFFFFF;\n\tselp.b32 %0, 1, 0, p;\n\t}" : "=r"(p));
    return p;
}

__device__ __forceinline__ void mma_f16_ss(uint32_t d_tmem, uint64_t a_desc,
                                           uint64_t b_desc, uint32_t idesc, uint32_t en) {
    asm volatile(
        "{\n\t.reg .pred p;\n\tsetp.ne.u32 p, %4, 0;\n\t"
        "tcgen05.mma.cta_group::1.kind::f16 [%0], %1, %2, %3, {%5, %5, %5, %5}, p;\n\t}"
        :: "r"(d_tmem), "l"(a_desc), "l"(b_desc), "r"(idesc), "r"(en), "r"(0u)
        : "memory");
}

// K-major SW128 smem descriptor (LBO=1, SBO=64, version=1, layout=SW128)
__device__ __forceinline__ uint64_t mk_desc(uint32_t saddr) {
    return ((uint64_t)2 << 61) | ((uint64_t)1 << 46) | ((uint64_t)64 << 32)
         | ((uint64_t)1 << 16) | ((uint64_t)(saddr >> 4) & 0x3FFF);
}

__device__ __forceinline__ void mbar_wait(uint32_t mb, int phase) {
    uint32_t done;
    asm volatile(
        "{\n\t.reg .pred p;\n\t"
        "mbarrier.try_wait.parity.acquire.cta.shared::cta.b64 p, [%1], %2;\n\t"
        "selp.b32 %0, 1, 0, p;\n\t}" : "=r"(done) : "r"(mb), "r"(phase) : "memory");
    if (!done) {
        asm volatile(
            "{\n\t.reg .pred P1;\n\tW0_%=:\n\t"
            "mbarrier.try_wait.parity.acquire.cta.shared::cta.b64 P1, [%0], %1, 0x989680;\n\t"
            "@P1 bra.uni W1_%=;\n\tbra.uni W0_%=;\n\tW1_%=:\n\t}"
            :: "r"(mb), "r"(phase) : "memory");
    }
}

__device__ __forceinline__ void cp16(uint32_t dst, const void* src) {
    asm volatile("cp.async.cg.shared.global [%0], [%1], 16;"
                 :: "r"(dst), "l"(src) : "memory");
}

// pack two int codes (0..255, high bytes zero) -> fp16x2 (q+1024), then subtract (1024+zero)
__device__ __forceinline__ uint32_t pack2(uint32_t a, uint32_t b, uint32_t hz2) {
    uint32_t r;
    asm("prmt.b32 %0, %1, %2, 0x5410;" : "=r"(r) : "r"(a), "r"(b));
    r += 0x64006400u;
    uint32_t o;
    asm("add.f16x2 %0, %1, %2;" : "=r"(o) : "r"(r), "r"(hz2));
    return o;
}
#endif

__global__ void xsplit_kernel(const float* __restrict__ x) {
    int i = blockIdx.x * blockDim.x + threadIdx.x;   // 0 .. 32*4096-1
    if (i >= MDIM * IN_DIM) return;
    float v  = x[i];
    __half h = __float2half_rn(v);
    __half l = __float2half_rn(v - __half2float(h));
    int m = i / IN_DIM, k = i % IN_DIM;
    g_A[m * IN_DIM + k]        = h;
    g_A[(m + 32) * IN_DIM + k] = l;
}

__global__ __launch_bounds__(256, 1)
void qgemm_tc(const int* __restrict__ wq,
              const int* __restrict__ zerop,
              const float* __restrict__ scalep,
              const float* __restrict__ bias,
              float* __restrict__ out)
{
#if TC_OK
    extern __shared__ char smem[];
    const uint32_t sb = (uint32_t)__cvta_generic_to_shared(smem);
    const int t   = threadIdx.x;
    const int wid = t >> 5;
    const int lid = t & 31;
    const int o0  = blockIdx.x * NTILE;

    const int zero = zerop[0];
    // hz2: -(1024+zero) in both fp16 lanes
    const __half  hzh = __int2half_rn(-1024 - zero);
    const __half2 hzv = __halves2half2(hzh, hzh);
    const uint32_t hz2 = *(const uint32_t*)&hzv;

    if (wid == 0) {
        asm volatile("tcgen05.alloc.cta_group::1.sync.aligned.shared::cta.b32 [%0], %1;"
                     :: "r"(sb + SM_TMEMPTR), "r"(128u) : "memory");
        asm volatile("tcgen05.relinquish_alloc_permit.cta_group::1.sync.aligned;");
    }
    if (t == 0) {
#pragma unroll
        for (int s = 0; s < NSTAGE; s++)
            asm volatile("mbarrier.init.shared.b64 [%0], 1;" :: "r"(sb + SM_MBAR(s)) : "memory");
    }
    // zero A pad rows (bytes 8192..16384 of each A stage)
    {
        uint4 z = make_uint4(0, 0, 0, 0);
#pragma unroll
        for (int s = 0; s < NSTAGE; s++)
            for (int i = t; i < 512; i += 256)
                *(uint4*)(smem + SM_A(s) + 8192 + i * 16) = z;
    }
    __syncthreads();
    uint32_t tmem;
    asm volatile("ld.shared.b32 %0, [%1];" : "=r"(tmem) : "r"(sb + SM_TMEMPTR));

    // ---- load maps (cp.async, 16B units)
    // B: thread -> row br = t>>1 (0..127), half bh = t&1; 8x16B contiguous from gmem
    const int br = t >> 1, bh = t & 1;
    const char* bsrc = (const char*)(wq + (size_t)(o0 + br) * IN_DIM + bh * 32);
    const uint32_t bdst[8] = {
        SW128((uint32_t)(br*128 + 0*16)), SW128((uint32_t)(br*128 + 1*16)),
        SW128((uint32_t)(br*128 + 2*16)), SW128((uint32_t)(br*128 + 3*16)),
        SW128((uint32_t)(br*128 + 4*16)), SW128((uint32_t)(br*128 + 5*16)),
        SW128((uint32_t)(br*128 + 6*16)), SW128((uint32_t)(br*128 + 7*16)) };
    // A: thread -> row ar = t>>2 (0..63), seg as = t&3 (32B); 2x16B
    const int ar = t >> 2, as = t & 3;
    const char* asrc = (const char*)g_A + (size_t)ar * IN_DIM * 2 + as * 32;
    const uint32_t a_sw0 = SW128((uint32_t)(ar*128 + as*32));
    const uint32_t a_sw1 = SW128((uint32_t)(ar*128 + as*32 + 16));

#define LOADS(c)                                                                  \
    do {                                                                          \
        const int _s = (c) % NSTAGE;                                              \
        const uint32_t stg = sb + SM_ST(_s) + bh * 16384;                         \
        const char* bs = bsrc + (size_t)(c) * 256;                                \
        _Pragma("unroll")                                                         \
        for (int j = 0; j < 8; j++) cp16(stg + bdst[j], bs + j * 16);             \
        const uint32_t atile = sb + SM_A(_s);                                     \
        cp16(atile + a_sw0, asrc + (size_t)(c) * 128);                            \
        cp16(atile + a_sw1, asrc + (size_t)(c) * 128 + 16);                       \
        asm volatile("cp.async.commit_group;" ::: "memory");                      \
    } while (0)

    int ph[NSTAGE] = {0, 0, 0};

    LOADS(0);
    LOADS(1);

    for (int c = 0; c < NCHUNK; c++) {
        const int st = c % NSTAGE;

        // gate: chunk c+1's buffers (stage (c+1)%3) were last read by MMA(c-2)
        if (c >= 2) {
            const int s1 = (c + 1) % NSTAGE;
            mbar_wait(sb + SM_MBAR(s1), ph[s1]);
            ph[s1] ^= 1;
        }

        if (c + 2 <= NCHUNK - 1) LOADS(c + 2);
        // wait group for chunk c (allow chunk c+1's group pending... plus c+2 just issued)
        if (c + 2 <= NCHUNK - 1)
            asm volatile("cp.async.wait_group 2;" ::: "memory");
        else
            asm volatile("cp.async.wait_group 0;" ::: "memory");
        __syncthreads();   // staging(st) fully landed for all threads

        // ---- convert: staging int32 -> fp16 B tile (both SW128)
        {
            const uint32_t stg = sb + SM_ST(st) + bh * 16384;
            const uint32_t bf  = sb + SM_BF(st);
#pragma unroll
            for (int j = 0; j < 4; j++) {
                uint32_t i0 = bdst[2*j], i1 = bdst[2*j+1];
                uint4 qa, qb;
                asm volatile("ld.shared.v4.b32 {%0,%1,%2,%3}, [%4];"
                    : "=r"(qa.x), "=r"(qa.y), "=r"(qa.z), "=r"(qa.w) : "r"(stg + i0));
                asm volatile("ld.shared.v4.b32 {%0,%1,%2,%3}, [%4];"
                    : "=r"(qb.x), "=r"(qb.y), "=r"(qb.z), "=r"(qb.w) : "r"(stg + i1));
                uint32_t h0 = pack2(qa.x, qa.y, hz2);
                uint32_t h1 = pack2(qa.z, qa.w, hz2);
                uint32_t h2 = pack2(qb.x, qb.y, hz2);
                uint32_t h3 = pack2(qb.z, qb.w, hz2);
                uint32_t off = SW128((uint32_t)(br*128 + bh*64 + j*16));
                asm volatile("st.shared.v4.b32 [%0], {%1,%2,%3,%4};"
                    :: "r"(bf + off), "r"(h0), "r"(h1), "r"(h2), "r"(h3) : "memory");
            }
        }

        asm volatile("fence.proxy.async.shared::cta;" ::: "memory");
        __syncthreads();

        if (wid == 0 && elect1()) {
            uint64_t ad = mk_desc(sb + SM_A(st));
            uint64_t bd = mk_desc(sb + SM_BF(st));
#pragma unroll
            for (int s = 0; s < KC / K_PER_MMA; s++)
                mma_f16_ss(tmem, ad + s * 2, bd + s * 2, MMA_IDESC,
                           (c > 0 || s > 0) ? 1u : 0u);
            asm volatile(
                "tcgen05.commit.cta_group::1.mbarrier::arrive::one.shared::cluster.b64 [%0];"
                :: "r"(sb + SM_MBAR(st)) : "memory");
        }
    }

    // ---- drain: MMAs of chunks NCHUNK-2, NCHUNK-1 not yet waited
    {
        const int sA = (NCHUNK - 2) % NSTAGE;
        mbar_wait(sb + SM_MBAR(sA), ph[sA]);
        const int sB = (NCHUNK - 1) % NSTAGE;
        mbar_wait(sb + SM_MBAR(sB), ph[sB]);
    }
    asm volatile("tcgen05.fence::after_thread_sync;" ::: "memory");
    __syncthreads();   // stage-0 A about to be reused as epilogue scratch

    // ---- epilogue: warp0 holds hi rows (m=lid), warp1 holds lo rows
    const float scale = scalep[0];
    float* Ep = (float*)(smem + EP_OFF);     // [32][33]
    float* Ys = (float*)(smem + YS_OFF);     // [32][132]

    for (int s = 0; s < 4; s++) {
        uint32_t d[32];
        if (wid < 2) {
            asm volatile(
                "tcgen05.ld.sync.aligned.32x32b.x32.b32 "
                "{%0,%1,%2,%3,%4,%5,%6,%7,%8,%9,%10,%11,%12,%13,%14,%15,"
                "%16,%17,%18,%19,%20,%21,%22,%23,%24,%25,%26,%27,%28,%29,%30,%31}, [%32];"
                : "=r"(d[0]), "=r"(d[1]), "=r"(d[2]), "=r"(d[3]), "=r"(d[4]), "=r"(d[5]),
                  "=r"(d[6]), "=r"(d[7]), "=r"(d[8]), "=r"(d[9]), "=r"(d[10]), "=r"(d[11]),
                  "=r"(d[12]), "=r"(d[13]), "=r"(d[14]), "=r"(d[15]), "=r"(d[16]), "=r"(d[17]),
                  "=r"(d[18]), "=r"(d[19]), "=r"(d[20]), "=r"(d[21]), "=r"(d[22]), "=r"(d[23]),
                  "=r"(d[24]), "=r"(d[25]), "=r"(d[26]), "=r"(d[27]), "=r"(d[28]), "=r"(d[29]),
                  "=r"(d[30]), "=r"(d[31])
                : "r"(tmem + s * 32));
            asm volatile("tcgen05.wait::ld.sync.aligned;" ::: "memory");
        }
        if (wid == 1) {
#pragma unroll
            for (int cc = 0; cc < 32; cc++) Ep[lid * 33 + cc] = __uint_as_float(d[cc]);
        }
        __syncthreads();
        if (wid == 0) {
#pragma unroll
            for (int cc = 0; cc < 32; cc++) {
                float hi = __uint_as_float(d[cc]);
                float lo = Ep[lid * 33 + cc];
                float b  = bias[o0 + s * 32 + cc];
                Ys[lid * 132 + s * 32 + cc] = fmaf(scale, hi + lo, b);
            }
        }
        __syncthreads();
    }

    // ---- coalesced store: 32 rows x 128 cols
    {
        const int m = t >> 3, q8 = t & 7;
#pragma unroll
        for (int i = 0; i < 4; i++) {
            const int q = q8 + 8 * i;
            float4 v = *(const float4*)(Ys + m * 132 + q * 4);
            *(float4*)(out + (size_t)m * OUT_DIM + o0 + q * 4) = v;
        }
    }

    __syncthreads();
    if (t == 0) {
#pragma unroll
        for (int s = 0; s < NSTAGE; s++)
            asm volatile("mbarrier.inval.shared.b64 [%0];" :: "r"(sb + SM_MBAR(s)) : "memory");
    }
    __syncthreads();
    if (wid == 0) {
        asm volatile("tcgen05.dealloc.cta_group::1.sync.aligned.b32 %0, %1;"
                     :: "r"(tmem), "r"(128u));
    }
#endif  // TC_OK
}

extern "C" void kernel_launch(void* const* d_in, const int* in_sizes, int n_in,
                              void* d_out, int out_size)
{
    const float* x     = (const float*)d_in[0];
    const int*   wq    = (const int*)  d_in[1];
    const int*   zero  = (const int*)  d_in[2];
    const float* scale = (const float*)d_in[3];
    const float* bias  = (const float*)d_in[4];
    float*       out   = (float*)d_out;

    cudaFuncSetAttribute(qgemm_tc, cudaFuncAttributeMaxDynamicSharedMemorySize, SMEM_TOTAL);

    xsplit_kernel<<<(MDIM * IN_DIM + 255) / 256, 256>>>(x);
    qgemm_tc<<<OUT_DIM / NTILE, 256, SMEM_TOTAL>>>(wq, zero, scale, bias, out);
}

// round 9
// speedup vs baseline: 2.6386x; 1.0171x over previous
#include <cuda_runtime.h>
#include <cuda_fp16.h>
#include <cstdint>

#define IN_DIM   4096
#define OUT_DIM  16384
#define MDIM     32

#define NTILE    128            // output cols per CTA
#define KC       64             // K per chunk
#define NCHUNK   (IN_DIM / KC)  // 64
#define NST_ST   4              // staging ring
#define NST_A    6              // A ring (8KB stages; desc footprint overlaps next stage: harmless)
#define NST_BF   2              // fp16 B ring
#define K_PER_MMA 16            // fp16: 32B per MMA step
#define MMA_M    128
#define MMA_IDESC ((1u<<4) | ((NTILE/8)<<17) | ((MMA_M/16)<<24))   // f32 acc, f16 in

// ---- dynamic smem layout (bytes)
#define SM_TMEMPTR 0
#define SM_MBAR(s) (8 + 8*(s))                    // 4 mbarriers
#define SM_A(s)    (1024 + (s)*8192)              // 6 x 8KB (+8KB guard after last)
#define SM_BF(s)   (58368 + (s)*16384)            // 2 x 16KB
#define SM_ST(s)   (91136 + (s)*32768)            // 4 x 32KB raw int32 staging
#define SMEM_TOTAL 222208
// epilogue scratch reuses A region after drain
#define EP_OFF     1024                           // [32][33] floats
#define YS_OFF     (1024 + 4352)                  // [32][132] floats

// arch-specific gate: tcgen05 only exists in the sm_103a-specific target.
#if defined(__CUDA_ARCH_FEAT_SM103_ALL) || defined(__CUDA_ARCH_FEAT_SM100_ALL) || \
    defined(__CUDA_ARCH_FEAT_SM101_ALL) || \
    (defined(__CUDA_ARCH_SPECIFIC__)) || (defined(__CUDA_ARCH_FAMILY_SPECIFIC__))
#define TC_OK 1
#else
#define TC_OK 0
#endif

// pre-converted A: rows 0..31 = hi(x), rows 32..63 = lo(x), fp16, row-major [64][4096]
__device__ __align__(1024) __half g_A[64 * IN_DIM];

#define SW128(o) ((o) ^ (((o) >> 3) & 0x70))

#if TC_OK
__device__ __forceinline__ uint32_t elect1() {
    uint32_t p;
    asm volatile("{\n\t.reg .pred p;\n\telect.sync _|p, 0xFFFFFFFF;\n\tselp.b32 %0, 1, 0, p;\n\t}" : "=r"(p));
    return p;
}

__device__ __forceinline__ void mma_f16_ss(uint32_t d_tmem, uint64_t a_desc,
                                           uint64_t b_desc, uint32_t idesc, uint32_t en) {
    asm volatile(
        "{\n\t.reg .pred p;\n\tsetp.ne.u32 p, %4, 0;\n\t"
        "tcgen05.mma.cta_group::1.kind::f16 [%0], %1, %2, %3, {%5, %5, %5, %5}, p;\n\t}"
        :: "r"(d_tmem), "l"(a_desc), "l"(b_desc), "r"(idesc), "r"(en), "r"(0u)
        : "memory");
}

// K-major SW128 smem descriptor (LBO=1, SBO=64, version=1, layout=SW128)
__device__ __forceinline__ uint64_t mk_desc(uint32_t saddr) {
    return ((uint64_t)2 << 61) | ((uint64_t)1 << 46) | ((uint64_t)64 << 32)
         | ((uint64_t)1 << 16) | ((uint64_t)(saddr >> 4) & 0x3FFF);
}

__device__ __forceinline__ void mbar_wait(uint32_t mb, int phase) {
    uint32_t done;
    asm volatile(
        "{\n\t.reg .pred p;\n\t"
        "mbarrier.try_wait.parity.acquire.cta.shared::cta.b64 p, [%1], %2;\n\t"
        "selp.b32 %0, 1, 0, p;\n\t}" : "=r"(done) : "r"(mb), "r"(phase) : "memory");
    if (!done) {
        asm volatile(
            "{\n\t.reg .pred P1;\n\tW0_%=:\n\t"
            "mbarrier.try_wait.parity.acquire.cta.shared::cta.b64 P1, [%0], %1, 0x989680;\n\t"
            "@P1 bra.uni W1_%=;\n\tbra.uni W0_%=;\n\tW1_%=:\n\t}"
            :: "r"(mb), "r"(phase) : "memory");
    }
}

__device__ __forceinline__ void cp16(uint32_t dst, const void* src) {
    asm volatile("cp.async.cg.shared.global [%0], [%1], 16;"
                 :: "r"(dst), "l"(src) : "memory");
}

// pack two int codes (0..255, high bytes zero) -> fp16x2 (q+1024), then subtract (1024+zero)
__device__ __forceinline__ uint32_t pack2(uint32_t a, uint32_t b, uint32_t hz2) {
    uint32_t r;
    asm("prmt.b32 %0, %1, %2, 0x5410;" : "=r"(r) : "r"(a), "r"(b));
    r += 0x64006400u;
    uint32_t o;
    asm("add.f16x2 %0, %1, %2;" : "=r"(o) : "r"(r), "r"(hz2));
    return o;
}
#endif

__global__ void xsplit_kernel(const float* __restrict__ x) {
    int i = blockIdx.x * blockDim.x + threadIdx.x;   // 0 .. 32*4096-1
    if (i >= MDIM * IN_DIM) return;
    float v  = x[i];
    __half h = __float2half_rn(v);
    __half l = __float2half_rn(v - __half2float(h));
    int m = i / IN_DIM, k = i % IN_DIM;
    g_A[m * IN_DIM + k]        = h;
    g_A[(m + 32) * IN_DIM + k] = l;
}

__global__ __launch_bounds__(256, 1)
void qgemm_tc(const int* __restrict__ wq,
              const int* __restrict__ zerop,
              const float* __restrict__ scalep,
              const float* __restrict__ bias,
              float* __restrict__ out)
{
#if TC_OK
    extern __shared__ char smem[];
    const uint32_t sb = (uint32_t)__cvta_generic_to_shared(smem);
    const int t   = threadIdx.x;
    const int wid = t >> 5;
    const int lid = t & 31;
    const int o0  = blockIdx.x * NTILE;

    const int zero = zerop[0];
    const __half  hzh = __int2half_rn(-1024 - zero);
    const __half2 hzv = __halves2half2(hzh, hzh);
    const uint32_t hz2 = *(const uint32_t*)&hzv;

    if (wid == 0) {
        asm volatile("tcgen05.alloc.cta_group::1.sync.aligned.shared::cta.b32 [%0], %1;"
                     :: "r"(sb + SM_TMEMPTR), "r"(128u) : "memory");
        asm volatile("tcgen05.relinquish_alloc_permit.cta_group::1.sync.aligned;");
    }
    if (t == 0) {
#pragma unroll
        for (int s = 0; s < 4; s++)
            asm volatile("mbarrier.init.shared.b64 [%0], 1;" :: "r"(sb + SM_MBAR(s)) : "memory");
    }
    __syncthreads();
    uint32_t tmem;
    asm volatile("ld.shared.b32 %0, [%1];" : "=r"(tmem) : "r"(sb + SM_TMEMPTR));

    // ---- load maps (cp.async, 16B units)
    // B: row br = t>>1 (0..127), half bh = t&1; 8x16B contiguous from gmem
    const int br = t >> 1, bh = t & 1;
    const char* bsrc = (const char*)(wq + (size_t)(o0 + br) * IN_DIM + bh * 32);
    const uint32_t bdst[8] = {
        SW128((uint32_t)(br*128 + 0*16)), SW128((uint32_t)(br*128 + 1*16)),
        SW128((uint32_t)(br*128 + 2*16)), SW128((uint32_t)(br*128 + 3*16)),
        SW128((uint32_t)(br*128 + 4*16)), SW128((uint32_t)(br*128 + 5*16)),
        SW128((uint32_t)(br*128 + 6*16)), SW128((uint32_t)(br*128 + 7*16)) };
    // A: row ar = t>>2 (0..63), seg as = t&3 (32B); 2x16B into 8KB stage
    const int ar = t >> 2, as = t & 3;
    const char* asrc = (const char*)g_A + (size_t)ar * IN_DIM * 2 + as * 32;
    const uint32_t a_sw0 = SW128((uint32_t)(ar*128 + as*32));
    const uint32_t a_sw1 = SW128((uint32_t)(ar*128 + as*32 + 16));

#define LOADS(c)                                                                  \
    do {                                                                          \
        const uint32_t stg = sb + SM_ST((c) & (NST_ST - 1)) + bh * 16384;         \
        const char* bs = bsrc + (size_t)(c) * 256;                                \
        _Pragma("unroll")                                                         \
        for (int j = 0; j < 8; j++) cp16(stg + bdst[j], bs + j * 16);             \
        const uint32_t atile = sb + SM_A((c) % NST_A);                            \
        cp16(atile + a_sw0, asrc + (size_t)(c) * 128);                            \
        cp16(atile + a_sw1, asrc + (size_t)(c) * 128 + 16);                       \
        asm volatile("cp.async.commit_group;" ::: "memory");                      \
    } while (0)

    int ph[4] = {0, 0, 0, 0};

    LOADS(0);
    LOADS(1);
    LOADS(2);

    for (int c = 0; c < NCHUNK; c++) {
        // gate bf(c&1) + A-ring + ordering: wait MMA(c-2) (fast path in steady state)
        if (c >= 2) {
            const int b = (c - 2) & 3;
            mbar_wait(sb + SM_MBAR(b), ph[b]);
            ph[b] ^= 1;
        }

        if (c + 3 < NCHUNK) LOADS(c + 3);

        // group(c) must be complete; up to 3 newer groups pending
        if (c + 3 < NCHUNK)
            asm volatile("cp.async.wait_group 3;" ::: "memory");
        else if (c + 2 < NCHUNK)
            asm volatile("cp.async.wait_group 2;" ::: "memory");
        else if (c + 1 < NCHUNK)
            asm volatile("cp.async.wait_group 1;" ::: "memory");
        else
            asm volatile("cp.async.wait_group 0;" ::: "memory");
        __syncthreads();   // staging(c%4) + A(c%6) landed for all threads

        // ---- convert: staging int32 -> fp16 B tile
        {
            const uint32_t stg = sb + SM_ST(c & (NST_ST - 1)) + bh * 16384;
            const uint32_t bf  = sb + SM_BF(c & 1);
#pragma unroll
            for (int j = 0; j < 4; j++) {
                uint32_t i0 = bdst[2*j], i1 = bdst[2*j+1];
                uint4 qa, qb;
                asm volatile("ld.shared.v4.b32 {%0,%1,%2,%3}, [%4];"
                    : "=r"(qa.x), "=r"(qa.y), "=r"(qa.z), "=r"(qa.w) : "r"(stg + i0));
                asm volatile("ld.shared.v4.b32 {%0,%1,%2,%3}, [%4];"
                    : "=r"(qb.x), "=r"(qb.y), "=r"(qb.z), "=r"(qb.w) : "r"(stg + i1));
                uint32_t h0 = pack2(qa.x, qa.y, hz2);
                uint32_t h1 = pack2(qa.z, qa.w, hz2);
                uint32_t h2 = pack2(qb.x, qb.y, hz2);
                uint32_t h3 = pack2(qb.z, qb.w, hz2);
                uint32_t off = SW128((uint32_t)(br*128 + bh*64 + j*16));
                asm volatile("st.shared.v4.b32 [%0], {%1,%2,%3,%4};"
                    :: "r"(bf + off), "r"(h0), "r"(h1), "r"(h2), "r"(h3) : "memory");
            }
        }

        asm volatile("fence.proxy.async.shared::cta;" ::: "memory");
        __syncthreads();

        if (wid == 0 && elect1()) {
            // A rows 64..127 of the descriptor footprint read junk (next stage) —
            // harmless: D rows 64..127 are never read.
            uint64_t ad = mk_desc(sb + SM_A(c % NST_A));
            uint64_t bd = mk_desc(sb + SM_BF(c & 1));
#pragma unroll
            for (int s = 0; s < KC / K_PER_MMA; s++)
                mma_f16_ss(tmem, ad + s * 2, bd + s * 2, MMA_IDESC,
                           (c > 0 || s > 0) ? 1u : 0u);
            asm volatile(
                "tcgen05.commit.cta_group::1.mbarrier::arrive::one.shared::cluster.b64 [%0];"
                :: "r"(sb + SM_MBAR(c & 3)) : "memory");
        }
    }

    // ---- drain: MMAs of chunks 62, 63
    {
        const int bA = (NCHUNK - 2) & 3;
        mbar_wait(sb + SM_MBAR(bA), ph[bA]);
        const int bB = (NCHUNK - 1) & 3;
        mbar_wait(sb + SM_MBAR(bB), ph[bB]);
    }
    asm volatile("tcgen05.fence::after_thread_sync;" ::: "memory");
    __syncthreads();   // A region about to be reused as epilogue scratch

    // ---- epilogue: warp0 holds hi rows (m=lid), warp1 holds lo rows
    const float scale = scalep[0];
    float* Ep = (float*)(smem + EP_OFF);     // [32][33]
    float* Ys = (float*)(smem + YS_OFF);     // [32][132]

    for (int s = 0; s < 4; s++) {
        uint32_t d[32];
        if (wid < 2) {
            asm volatile(
                "tcgen05.ld.sync.aligned.32x32b.x32.b32 "
                "{%0,%1,%2,%3,%4,%5,%6,%7,%8,%9,%10,%11,%12,%13,%14,%15,"
                "%16,%17,%18,%19,%20,%21,%22,%23,%24,%25,%26,%27,%28,%29,%30,%31}, [%32];"
                : "=r"(d[0]), "=r"(d[1]), "=r"(d[2]), "=r"(d[3]), "=r"(d[4]), "=r"(d[5]),
                  "=r"(d[6]), "=r"(d[7]), "=r"(d[8]), "=r"(d[9]), "=r"(d[10]), "=r"(d[11]),
                  "=r"(d[12]), "=r"(d[13]), "=r"(d[14]), "=r"(d[15]), "=r"(d[16]), "=r"(d[17]),
                  "=r"(d[18]), "=r"(d[19]), "=r"(d[20]), "=r"(d[21]), "=r"(d[22]), "=r"(d[23]),
                  "=r"(d[24]), "=r"(d[25]), "=r"(d[26]), "=r"(d[27]), "=r"(d[28]), "=r"(d[29]),
                  "=r"(d[30]), "=r"(d[31])
                : "r"(tmem + s * 32));
            asm volatile("tcgen05.wait::ld.sync.aligned;" ::: "memory");
        }
        if (wid == 1) {
#pragma unroll
            for (int cc = 0; cc < 32; cc++) Ep[lid * 33 + cc] = __uint_as_float(d[cc]);
        }
        __syncthreads();
        if (wid == 0) {
#pragma unroll
            for (int cc = 0; cc < 32; cc++) {
                float hi = __uint_as_float(d[cc]);
                float lo = Ep[lid * 33 + cc];
                float b  = bias[o0 + s * 32 + cc];
                Ys[lid * 132 + s * 32 + cc] = fmaf(scale, hi + lo, b);
            }
        }
        __syncthreads();
    }

    // ---- coalesced store: 32 rows x 128 cols
    {
        const int m = t >> 3, q8 = t & 7;
#pragma unroll
        for (int i = 0; i < 4; i++) {
            const int q = q8 + 8 * i;
            float4 v = *(const float4*)(Ys + m * 132 + q * 4);
            *(float4*)(out + (size_t)m * OUT_DIM + o0 + q * 4) = v;
        }
    }

    __syncthreads();
    if (t == 0) {
#pragma unroll
        for (int s = 0; s < 4; s++)
            asm volatile("mbarrier.inval.shared.b64 [%0];" :: "r"(sb + SM_MBAR(s)) : "memory");
    }
    __syncthreads();
    if (wid == 0) {
        asm volatile("tcgen05.dealloc.cta_group::1.sync.aligned.b32 %0, %1;"
                     :: "r"(tmem), "r"(128u));
    }
#endif  // TC_OK
}

extern "C" void kernel_launch(void* const* d_in, const int* in_sizes, int n_in,
                              void* d_out, int out_size)
{
    const float* x     = (const float*)d_in[0];
    const int*   wq    = (const int*)  d_in[1];
    const int*   zero  = (const int*)  d_in[2];
    const float* scale = (const float*)d_in[3];
    const float* bias  = (const float*)d_in[4];
    float*       out   = (float*)d_out;

    cudaFuncSetAttribute(qgemm_tc, cudaFuncAttributeMaxDynamicSharedMemorySize, SMEM_TOTAL);

    xsplit_kernel<<<(MDIM * IN_DIM + 255) / 256, 256>>>(x);
    qgemm_tc<<<OUT_DIM / NTILE, 256, SMEM_TOTAL>>>(wq, zero, scale, bias, out);
}

// round 10
// speedup vs baseline: 4.5655x; 1.7303x over previous
#include <cuda_runtime.h>
#include <cuda_fp16.h>
#include <cstdint>

#define IN_DIM   4096
#define OUT_DIM  16384
#define MDIM     32

#define NTILE    64             // output cols per CTA
#define KC       64             // K per chunk
#define NCHUNK   (IN_DIM / KC)  // 64
#define NST_ST   3              // staging ring (linear layout, 272B rows)
#define NST_A    4              // A ring (8KB SW128 stages)
#define K_PER_MMA 16
#define MMA_M    128
#define MMA_IDESC ((1u<<4) | ((NTILE/8)<<17) | ((MMA_M/16)<<24))   // f32 acc, f16 in

#define ST_ROWB  272            // staging row stride (256 data + 16 pad)
#define ST_SIZE  (64 * ST_ROWB) // 17408 per stage

// ---- dynamic smem layout (bytes)
#define SM_TMEMPTR 0
#define SM_MBAR(s) (8 + 8*(s))                    // 4 mbarriers
#define SM_A(s)    (1024 + (s)*8192)              // 4 x 8KB fp16 A
#define SM_BF(s)   (33792 + (s)*8192)             // 2 x 8KB fp16 B
#define SM_ST(s)   (50176 + (s)*ST_SIZE)          // 3 x 17408 raw int32 staging
#define SMEM_TOTAL 102400                          // 100KB -> 2 CTAs/SM
// epilogue scratch reuses A region after drain
#define EP_OFF     1024                           // [32][33] floats
#define YS_OFF     (1024 + 4352)                  // [32][68] floats

// arch-specific gate: tcgen05 only exists in the sm_103a-specific target.
#if defined(__CUDA_ARCH_FEAT_SM103_ALL) || defined(__CUDA_ARCH_FEAT_SM100_ALL) || \
    defined(__CUDA_ARCH_FEAT_SM101_ALL) || \
    (defined(__CUDA_ARCH_SPECIFIC__)) || (defined(__CUDA_ARCH_FAMILY_SPECIFIC__))
#define TC_OK 1
#else
#define TC_OK 0
#endif

// pre-converted A: rows 0..31 = hi(x), rows 32..63 = lo(x), fp16, row-major [64][4096]
__device__ __align__(1024) __half g_A[64 * IN_DIM];

#define SW128(o) ((o) ^ (((o) >> 3) & 0x70))

#if TC_OK
__device__ __forceinline__ uint32_t elect1() {
    uint32_t p;
    asm volatile("{\n\t.reg .pred p;\n\telect.sync _|p, 0xFFFFFFFF;\n\tselp.b32 %0, 1, 0, p;\n\t}" : "=r"(p));
    return p;
}

__device__ __forceinline__ void mma_f16_ss(uint32_t d_tmem, uint64_t a_desc,
                                           uint64_t b_desc, uint32_t idesc, uint32_t en) {
    asm volatile(
        "{\n\t.reg .pred p;\n\tsetp.ne.u32 p, %4, 0;\n\t"
        "tcgen05.mma.cta_group::1.kind::f16 [%0], %1, %2, %3, {%5, %5, %5, %5}, p;\n\t}"
        :: "r"(d_tmem), "l"(a_desc), "l"(b_desc), "r"(idesc), "r"(en), "r"(0u)
        : "memory");
}

// K-major SW128 smem descriptor (LBO=1, SBO=64, version=1, layout=SW128)
__device__ __forceinline__ uint64_t mk_desc(uint32_t saddr) {
    return ((uint64_t)2 << 61) | ((uint64_t)1 << 46) | ((uint64_t)64 << 32)
         | ((uint64_t)1 << 16) | ((uint64_t)(saddr >> 4) & 0x3FFF);
}

__device__ __forceinline__ void mbar_wait(uint32_t mb, int phase) {
    uint32_t done;
    asm volatile(
        "{\n\t.reg .pred p;\n\t"
        "mbarrier.try_wait.parity.acquire.cta.shared::cta.b64 p, [%1], %2;\n\t"
        "selp.b32 %0, 1, 0, p;\n\t}" : "=r"(done) : "r"(mb), "r"(phase) : "memory");
    if (!done) {
        asm volatile(
            "{\n\t.reg .pred P1;\n\tW0_%=:\n\t"
            "mbarrier.try_wait.parity.acquire.cta.shared::cta.b64 P1, [%0], %1, 0x989680;\n\t"
            "@P1 bra.uni W1_%=;\n\tbra.uni W0_%=;\n\tW1_%=:\n\t}"
            :: "r"(mb), "r"(phase) : "memory");
    }
}

__device__ __forceinline__ void cp16(uint32_t dst, const void* src) {
    asm volatile("cp.async.cg.shared.global [%0], [%1], 16;"
                 :: "r"(dst), "l"(src) : "memory");
}

// pack two int codes (0..255, high bytes zero) -> fp16x2 (q+1024), then subtract (1024+zero)
__device__ __forceinline__ uint32_t pack2(uint32_t a, uint32_t b, uint32_t hz2) {
    uint32_t r;
    asm("prmt.b32 %0, %1, %2, 0x5410;" : "=r"(r) : "r"(a), "r"(b));
    r += 0x64006400u;
    uint32_t o;
    asm("add.f16x2 %0, %1, %2;" : "=r"(o) : "r"(r), "r"(hz2));
    return o;
}
#endif

__global__ void xsplit_kernel(const float* __restrict__ x) {
    int i = blockIdx.x * blockDim.x + threadIdx.x;   // 0 .. 32*4096-1
    if (i >= MDIM * IN_DIM) return;
    float v  = x[i];
    __half h = __float2half_rn(v);
    __half l = __float2half_rn(v - __half2float(h));
    int m = i / IN_DIM, k = i % IN_DIM;
    g_A[m * IN_DIM + k]        = h;
    g_A[(m + 32) * IN_DIM + k] = l;
}

__global__ __launch_bounds__(256, 2)
void qgemm_tc(const int* __restrict__ wq,
              const int* __restrict__ zerop,
              const float* __restrict__ scalep,
              const float* __restrict__ bias,
              float* __restrict__ out)
{
#if TC_OK
    extern __shared__ char smem[];
    const uint32_t sb = (uint32_t)__cvta_generic_to_shared(smem);
    const int t   = threadIdx.x;
    const int wid = t >> 5;
    const int lid = t & 31;
    const int o0  = blockIdx.x * NTILE;

    const int zero = zerop[0];
    const __half  hzh = __int2half_rn(-1024 - zero);
    const __half2 hzv = __halves2half2(hzh, hzh);
    const uint32_t hz2 = *(const uint32_t*)&hzv;

    if (wid == 0) {
        asm volatile("tcgen05.alloc.cta_group::1.sync.aligned.shared::cta.b32 [%0], %1;"
                     :: "r"(sb + SM_TMEMPTR), "r"(64u) : "memory");
        asm volatile("tcgen05.relinquish_alloc_permit.cta_group::1.sync.aligned;");
    }
    if (t == 0) {
#pragma unroll
        for (int s = 0; s < 4; s++)
            asm volatile("mbarrier.init.shared.b64 [%0], 1;" :: "r"(sb + SM_MBAR(s)) : "memory");
    }
    __syncthreads();
    uint32_t tmem;
    asm volatile("ld.shared.b32 %0, [%1];" : "=r"(tmem) : "r"(sb + SM_TMEMPTR));

    // ---- load maps (each thread converts exactly what it loads -> no producer barrier)
    // B: seg s16 = t&15 (16B col segment), row group rg = t>>4 (4 rows each)
    const int s16 = t & 15, rg = t >> 4;
    const char* bsrc = (const char*)wq + (size_t)(o0 + rg * 4) * IN_DIM * 4 + s16 * 16;
    // staging dst for the 4 rows (linear, 272B row stride)
    const uint32_t st_d0 = (uint32_t)((rg * 4 + 0) * ST_ROWB + s16 * 16);
    const uint32_t st_d1 = (uint32_t)((rg * 4 + 1) * ST_ROWB + s16 * 16);
    const uint32_t st_d2 = (uint32_t)((rg * 4 + 2) * ST_ROWB + s16 * 16);
    const uint32_t st_d3 = (uint32_t)((rg * 4 + 3) * ST_ROWB + s16 * 16);
    // A: row ar = t>>2 (0..63), seg as = t&3 (32B); 2x16B, SW128
    const int ar = t >> 2, as = t & 3;
    const char* asrc = (const char*)g_A + (size_t)ar * IN_DIM * 2 + as * 32;
    const uint32_t a_sw0 = SW128((uint32_t)(ar*128 + as*32));
    const uint32_t a_sw1 = SW128((uint32_t)(ar*128 + as*32 + 16));

#define LOADS(c)                                                                  \
    do {                                                                          \
        const uint32_t stg = sb + SM_ST((c) % NST_ST);                            \
        const char* bs = bsrc + (size_t)(c) * 256;                                \
        cp16(stg + st_d0, bs);                                                    \
        cp16(stg + st_d1, bs + (size_t)IN_DIM * 4);                               \
        cp16(stg + st_d2, bs + (size_t)IN_DIM * 8);                               \
        cp16(stg + st_d3, bs + (size_t)IN_DIM * 12);                              \
        const uint32_t atile = sb + SM_A((c) & (NST_A - 1));                      \
        cp16(atile + a_sw0, asrc + (size_t)(c) * 128);                            \
        cp16(atile + a_sw1, asrc + (size_t)(c) * 128 + 16);                       \
        asm volatile("cp.async.commit_group;" ::: "memory");                      \
    } while (0)

    int ph[4] = {0, 0, 0, 0};

    LOADS(0);
    LOADS(1);

    for (int c = 0; c < NCHUNK; c++) {
        // gate bf(c&1) reuse + A stage reuse on MMA(c-2) (fast path in steady state)
        if (c >= 2) {
            const int b = (c - 2) & 3;
            mbar_wait(sb + SM_MBAR(b), ph[b]);
            ph[b] ^= 1;
        }

        if (c + 2 < NCHUNK) LOADS(c + 2);

        // this thread's group for chunk c complete (covers the staging it converts)
        if (c + 2 < NCHUNK)
            asm volatile("cp.async.wait_group 2;" ::: "memory");
        else if (c + 1 < NCHUNK)
            asm volatile("cp.async.wait_group 1;" ::: "memory");
        else
            asm volatile("cp.async.wait_group 0;" ::: "memory");

        // ---- convert own staging bytes -> fp16 B tile (SW128). No barrier needed first.
        {
            const uint32_t stg = sb + SM_ST(c % NST_ST);
            const uint32_t bf  = sb + SM_BF(c & 1);
#pragma unroll
            for (int j = 0; j < 4; j++) {
                const int row = rg * 4 + j;
                uint4 q4;
                asm volatile("ld.shared.v4.b32 {%0,%1,%2,%3}, [%4];"
                    : "=r"(q4.x), "=r"(q4.y), "=r"(q4.z), "=r"(q4.w)
                    : "r"(stg + (uint32_t)(row * ST_ROWB + s16 * 16)));
                uint32_t h0 = pack2(q4.x, q4.y, hz2);
                uint32_t h1 = pack2(q4.z, q4.w, hz2);
                uint32_t off = SW128((uint32_t)(row * 128 + s16 * 8));
                asm volatile("st.shared.v2.b32 [%0], {%1,%2};"
                    :: "r"(bf + off), "r"(h0), "r"(h1) : "memory");
            }
        }

        asm volatile("fence.proxy.async.shared::cta;" ::: "memory");
        __syncthreads();   // all converts + all threads' A cp.async visible

        if (wid == 0 && elect1()) {
            // A desc footprint rows 64..127 read the next stage as junk -> only
            // pollutes D rows 64..127, which are never read out.
            uint64_t ad = mk_desc(sb + SM_A(c & (NST_A - 1)));
            uint64_t bd = mk_desc(sb + SM_BF(c & 1));
#pragma unroll
            for (int s = 0; s < KC / K_PER_MMA; s++)
                mma_f16_ss(tmem, ad + s * 2, bd + s * 2, MMA_IDESC,
                           (c > 0 || s > 0) ? 1u : 0u);
            asm volatile(
                "tcgen05.commit.cta_group::1.mbarrier::arrive::one.shared::cluster.b64 [%0];"
                :: "r"(sb + SM_MBAR(c & 3)) : "memory");
        }
    }

    // ---- drain: MMAs of chunks 62, 63
    {
        const int bA = (NCHUNK - 2) & 3;
        mbar_wait(sb + SM_MBAR(bA), ph[bA]);
        const int bB = (NCHUNK - 1) & 3;
        mbar_wait(sb + SM_MBAR(bB), ph[bB]);
    }
    asm volatile("tcgen05.fence::after_thread_sync;" ::: "memory");
    __syncthreads();   // A region about to be reused as epilogue scratch

    // ---- epilogue: warp0 holds hi rows (m=lid), warp1 holds lo rows
    const float scale = scalep[0];
    float* Ep = (float*)(smem + EP_OFF);     // [32][33]
    float* Ys = (float*)(smem + YS_OFF);     // [32][68]

    for (int s = 0; s < 2; s++) {
        uint32_t d[32];
        if (wid < 2) {
            asm volatile(
                "tcgen05.ld.sync.aligned.32x32b.x32.b32 "
                "{%0,%1,%2,%3,%4,%5,%6,%7,%8,%9,%10,%11,%12,%13,%14,%15,"
                "%16,%17,%18,%19,%20,%21,%22,%23,%24,%25,%26,%27,%28,%29,%30,%31}, [%32];"
                : "=r"(d[0]), "=r"(d[1]), "=r"(d[2]), "=r"(d[3]), "=r"(d[4]), "=r"(d[5]),
                  "=r"(d[6]), "=r"(d[7]), "=r"(d[8]), "=r"(d[9]), "=r"(d[10]), "=r"(d[11]),
                  "=r"(d[12]), "=r"(d[13]), "=r"(d[14]), "=r"(d[15]), "=r"(d[16]), "=r"(d[17]),
                  "=r"(d[18]), "=r"(d[19]), "=r"(d[20]), "=r"(d[21]), "=r"(d[22]), "=r"(d[23]),
                  "=r"(d[24]), "=r"(d[25]), "=r"(d[26]), "=r"(d[27]), "=r"(d[28]), "=r"(d[29]),
                  "=r"(d[30]), "=r"(d[31])
                : "r"(tmem + s * 32));
            asm volatile("tcgen05.wait::ld.sync.aligned;" ::: "memory");
        }
        if (wid == 1) {
#pragma unroll
            for (int cc = 0; cc < 32; cc++) Ep[lid * 33 + cc] = __uint_as_float(d[cc]);
        }
        __syncthreads();
        if (wid == 0) {
#pragma unroll
            for (int cc = 0; cc < 32; cc++) {
                float hi = __uint_as_float(d[cc]);
                float lo = Ep[lid * 33 + cc];
                float b  = bias[o0 + s * 32 + cc];
                Ys[lid * 68 + s * 32 + cc] = fmaf(scale, hi + lo, b);
            }
        }
        __syncthreads();
    }

    // ---- coalesced store: 32 rows x 64 cols
    {
        const int m = t >> 3, q8 = t & 7;
#pragma unroll
        for (int i = 0; i < 2; i++) {
            const int q = q8 + 8 * i;
            float4 v = *(const float4*)(Ys + m * 68 + q * 4);
            *(float4*)(out + (size_t)m * OUT_DIM + o0 + q * 4) = v;
        }
    }

    __syncthreads();
    if (t == 0) {
#pragma unroll
        for (int s = 0; s < 4; s++)
            asm volatile("mbarrier.inval.shared.b64 [%0];" :: "r"(sb + SM_MBAR(s)) : "memory");
    }
    __syncthreads();
    if (wid == 0) {
        asm volatile("tcgen05.dealloc.cta_group::1.sync.aligned.b32 %0, %1;"
                     :: "r"(tmem), "r"(64u));
    }
#endif  // TC_OK
}

extern "C" void kernel_launch(void* const* d_in, const int* in_sizes, int n_in,
                              void* d_out, int out_size)
{
    const float* x     = (const float*)d_in[0];
    const int*   wq    = (const int*)  d_in[1];
    const int*   zero  = (const int*)  d_in[2];
    const float* scale = (const float*)d_in[3];
    const float* bias  = (const float*)d_in[4];
    float*       out   = (float*)d_out;

    cudaFuncSetAttribute(qgemm_tc, cudaFuncAttributeMaxDynamicSharedMemorySize, SMEM_TOTAL);

    xsplit_kernel<<<(MDIM * IN_DIM + 255) / 256, 256>>>(x);
    qgemm_tc<<<OUT_DIM / NTILE, 256, SMEM_TOTAL>>>(wq, zero, scale, bias, out);
}

// round 11
// speedup vs baseline: 5.3207x; 1.1654x over previous
#include <cuda_runtime.h>
#include <cuda_fp16.h>
#include <cstdint>

#define IN_DIM   4096
#define OUT_DIM  16384
#define MDIM     32

#define NTILE    64             // output cols per CTA
#define KC       64             // K per chunk
#define NCHUNK   (IN_DIM / KC)  // 64
#define NST_ST   3              // staging ring (linear layout, 272B rows)
#define NST_A    4              // A ring (8KB SW128 stages)
#define K_PER_MMA 16
#define MMA_M    128
#define MMA_IDESC ((1u<<4) | ((NTILE/8)<<17) | ((MMA_M/16)<<24))   // f32 acc, f16 in

#define NTHREADS 288            // 8 producer warps + 1 MMA warp

#define ST_ROWB  272            // staging row stride (256 data + 16 pad)
#define ST_SIZE  (64 * ST_ROWB) // 17408 per stage

// ---- dynamic smem layout (bytes)
#define SM_TMEMPTR 0
#define SM_MBAR(s) (8 + 8*(s))                    // 0..3: mma commit, 4..5: full
#define SM_A(s)    (1024 + (s)*8192)              // 4 x 8KB fp16 A
#define SM_BF(s)   (33792 + (s)*8192)             // 2 x 8KB fp16 B
#define SM_ST(s)   (50176 + (s)*ST_SIZE)          // 3 x 17408 raw int32 staging
#define SMEM_TOTAL 102400                          // 100KB -> 2 CTAs/SM
// epilogue scratch reuses A region after drain
#define EP_OFF     1024                           // [32][33] floats
#define YS_OFF     (1024 + 4352)                  // [32][68] floats

// arch-specific gate: tcgen05 only exists in the sm_103a-specific target.
#if defined(__CUDA_ARCH_FEAT_SM103_ALL) || defined(__CUDA_ARCH_FEAT_SM100_ALL) || \
    defined(__CUDA_ARCH_FEAT_SM101_ALL) || \
    (defined(__CUDA_ARCH_SPECIFIC__)) || (defined(__CUDA_ARCH_FAMILY_SPECIFIC__))
#define TC_OK 1
#else
#define TC_OK 0
#endif

// pre-converted A: rows 0..31 = hi(x), rows 32..63 = lo(x), fp16, row-major [64][4096]
__device__ __align__(1024) __half g_A[64 * IN_DIM];

#define SW128(o) ((o) ^ (((o) >> 3) & 0x70))

#if TC_OK
__device__ __forceinline__ uint32_t elect1() {
    uint32_t p;
    asm volatile("{\n\t.reg .pred p;\n\telect.sync _|p, 0xFFFFFFFF;\n\tselp.b32 %0, 1, 0, p;\n\t}" : "=r"(p));
    return p;
}

__device__ __forceinline__ void mma_f16_ss(uint32_t d_tmem, uint64_t a_desc,
                                           uint64_t b_desc, uint32_t idesc, uint32_t en) {
    asm volatile(
        "{\n\t.reg .pred p;\n\tsetp.ne.u32 p, %4, 0;\n\t"
        "tcgen05.mma.cta_group::1.kind::f16 [%0], %1, %2, %3, {%5, %5, %5, %5}, p;\n\t}"
        :: "r"(d_tmem), "l"(a_desc), "l"(b_desc), "r"(idesc), "r"(en), "r"(0u)
        : "memory");
}

// K-major SW128 smem descriptor (LBO=1, SBO=64, version=1, layout=SW128)
__device__ __forceinline__ uint64_t mk_desc(uint32_t saddr) {
    return ((uint64_t)2 << 61) | ((uint64_t)1 << 46) | ((uint64_t)64 << 32)
         | ((uint64_t)1 << 16) | ((uint64_t)(saddr >> 4) & 0x3FFF);
}

__device__ __forceinline__ void mbar_wait(uint32_t mb, int phase) {
    uint32_t done;
    asm volatile(
        "{\n\t.reg .pred p;\n\t"
        "mbarrier.try_wait.parity.acquire.cta.shared::cta.b64 p, [%1], %2;\n\t"
        "selp.b32 %0, 1, 0, p;\n\t}" : "=r"(done) : "r"(mb), "r"(phase) : "memory");
    if (!done) {
        asm volatile(
            "{\n\t.reg .pred P1;\n\tW0_%=:\n\t"
            "mbarrier.try_wait.parity.acquire.cta.shared::cta.b64 P1, [%0], %1, 0x989680;\n\t"
            "@P1 bra.uni W1_%=;\n\tbra.uni W0_%=;\n\tW1_%=:\n\t}"
            :: "r"(mb), "r"(phase) : "memory");
    }
}

__device__ __forceinline__ void cp16(uint32_t dst, const void* src) {
    asm volatile("cp.async.cg.shared.global [%0], [%1], 16;"
                 :: "r"(dst), "l"(src) : "memory");
}

// pack two int codes (0..255, high bytes zero) -> fp16x2 (q+1024), then subtract (1024+zero)
__device__ __forceinline__ uint32_t pack2(uint32_t a, uint32_t b, uint32_t hz2) {
    uint32_t r;
    asm("prmt.b32 %0, %1, %2, 0x5410;" : "=r"(r) : "r"(a), "r"(b));
    r += 0x64006400u;
    uint32_t o;
    asm("add.f16x2 %0, %1, %2;" : "=r"(o) : "r"(r), "r"(hz2));
    return o;
}
#endif

__global__ void xsplit_kernel(const float* __restrict__ x) {
    int i = blockIdx.x * blockDim.x + threadIdx.x;   // 0 .. 32*4096-1
    if (i >= MDIM * IN_DIM) return;
    float v  = x[i];
    __half h = __float2half_rn(v);
    __half l = __float2half_rn(v - __half2float(h));
    int m = i / IN_DIM, k = i % IN_DIM;
    g_A[m * IN_DIM + k]        = h;
    g_A[(m + 32) * IN_DIM + k] = l;
}

__global__ __launch_bounds__(NTHREADS, 2)
void qgemm_tc(const int* __restrict__ wq,
              const int* __restrict__ zerop,
              const float* __restrict__ scalep,
              const float* __restrict__ bias,
              float* __restrict__ out)
{
#if TC_OK
    extern __shared__ char smem[];
    const uint32_t sb = (uint32_t)__cvta_generic_to_shared(smem);
    const int t   = threadIdx.x;
    const int wid = t >> 5;
    const int lid = t & 31;
    const int o0  = blockIdx.x * NTILE;

    const int zero = zerop[0];
    const __half  hzh = __int2half_rn(-1024 - zero);
    const __half2 hzv = __halves2half2(hzh, hzh);
    const uint32_t hz2 = *(const uint32_t*)&hzv;

    if (wid == 0) {
        asm volatile("tcgen05.alloc.cta_group::1.sync.aligned.shared::cta.b32 [%0], %1;"
                     :: "r"(sb + SM_TMEMPTR), "r"(64u) : "memory");
        asm volatile("tcgen05.relinquish_alloc_permit.cta_group::1.sync.aligned;");
    }
    if (t == 0) {
#pragma unroll
        for (int s = 0; s < 4; s++)    // mma-commit mbars, count 1
            asm volatile("mbarrier.init.shared.b64 [%0], 1;" :: "r"(sb + SM_MBAR(s)) : "memory");
#pragma unroll
        for (int s = 4; s < 6; s++)    // full mbars, count 8 (one per producer warp)
            asm volatile("mbarrier.init.shared.b64 [%0], 8;" :: "r"(sb + SM_MBAR(s)) : "memory");
    }
    __syncthreads();
    uint32_t tmem;
    asm volatile("ld.shared.b32 %0, [%1];" : "=r"(tmem) : "r"(sb + SM_TMEMPTR));

    if (wid < 8) {
        // ================= PRODUCER WARPS =================
        // B: seg s16 = t&15 (16B col segment), row group rg = t>>4 (4 rows each)
        const int s16 = t & 15, rg = t >> 4;
        const char* bsrc = (const char*)wq + (size_t)(o0 + rg * 4) * IN_DIM * 4 + s16 * 16;
        const uint32_t st_d0 = (uint32_t)((rg * 4 + 0) * ST_ROWB + s16 * 16);
        const uint32_t st_d1 = (uint32_t)((rg * 4 + 1) * ST_ROWB + s16 * 16);
        const uint32_t st_d2 = (uint32_t)((rg * 4 + 2) * ST_ROWB + s16 * 16);
        const uint32_t st_d3 = (uint32_t)((rg * 4 + 3) * ST_ROWB + s16 * 16);
        // A: row ar = t>>2 (0..63), seg as = t&3 (32B); 2x16B, SW128
        const int ar = t >> 2, as = t & 3;
        const char* asrc = (const char*)g_A + (size_t)ar * IN_DIM * 2 + as * 32;
        const uint32_t a_sw0 = SW128((uint32_t)(ar*128 + as*32));
        const uint32_t a_sw1 = SW128((uint32_t)(ar*128 + as*32 + 16));

#define LOADS(c)                                                                  \
    do {                                                                          \
        const uint32_t stg = sb + SM_ST((c) % NST_ST);                            \
        const char* bs = bsrc + (size_t)(c) * 256;                                \
        cp16(stg + st_d0, bs);                                                    \
        cp16(stg + st_d1, bs + (size_t)IN_DIM * 4);                               \
        cp16(stg + st_d2, bs + (size_t)IN_DIM * 8);                               \
        cp16(stg + st_d3, bs + (size_t)IN_DIM * 12);                              \
        const uint32_t atile = sb + SM_A((c) & (NST_A - 1));                      \
        cp16(atile + a_sw0, asrc + (size_t)(c) * 128);                            \
        cp16(atile + a_sw1, asrc + (size_t)(c) * 128 + 16);                       \
        asm volatile("cp.async.commit_group;" ::: "memory");                      \
    } while (0)

        int ph[4] = {0, 0, 0, 0};

        LOADS(0);
        LOADS(1);

        for (int c = 0; c < NCHUNK; c++) {
            // gate bf(c&1) + A-ring reuse on MMA(c-2) completion
            if (c >= 2) {
                const int b = (c - 2) & 3;
                mbar_wait(sb + SM_MBAR(b), ph[b]);
                ph[b] ^= 1;
            }

            if (c + 2 < NCHUNK) LOADS(c + 2);

            if (c + 2 < NCHUNK)
                asm volatile("cp.async.wait_group 2;" ::: "memory");
            else if (c + 1 < NCHUNK)
                asm volatile("cp.async.wait_group 1;" ::: "memory");
            else
                asm volatile("cp.async.wait_group 0;" ::: "memory");

            // convert own staging bytes -> fp16 B tile (SW128)
            {
                const uint32_t stg = sb + SM_ST(c % NST_ST);
                const uint32_t bf  = sb + SM_BF(c & 1);
#pragma unroll
                for (int j = 0; j < 4; j++) {
                    const int row = rg * 4 + j;
                    uint4 q4;
                    asm volatile("ld.shared.v4.b32 {%0,%1,%2,%3}, [%4];"
                        : "=r"(q4.x), "=r"(q4.y), "=r"(q4.z), "=r"(q4.w)
                        : "r"(stg + (uint32_t)(row * ST_ROWB + s16 * 16)));
                    uint32_t h0 = pack2(q4.x, q4.y, hz2);
                    uint32_t h1 = pack2(q4.z, q4.w, hz2);
                    uint32_t off = SW128((uint32_t)(row * 128 + s16 * 8));
                    asm volatile("st.shared.v2.b32 [%0], {%1,%2};"
                        :: "r"(bf + off), "r"(h0), "r"(h1) : "memory");
                }
            }

            // signal: this warp's slice of chunk c (B converted + A cp.async complete)
            asm volatile("fence.proxy.async.shared::cta;" ::: "memory");
            __syncwarp();
            if (elect1())
                asm volatile("mbarrier.arrive.shared.b64 _, [%0];"
                             :: "r"(sb + SM_MBAR(4 + (c & 1))) : "memory");
            // NO waiting on peers or MMA issue: straight to chunk c+1
        }

        // drain: MMAs of chunks 62, 63 (needed before epilogue TMEM read)
        {
            const int bA = (NCHUNK - 2) & 3;
            mbar_wait(sb + SM_MBAR(bA), ph[bA]);
            const int bB = (NCHUNK - 1) & 3;
            mbar_wait(sb + SM_MBAR(bB), ph[bB]);
        }
        asm volatile("tcgen05.fence::after_thread_sync;" ::: "memory");
    } else {
        // ================= MMA WARP (wid == 8) =================
        int phf[2] = {0, 0};
        for (int c = 0; c < NCHUNK; c++) {
            const int f = c & 1;
            mbar_wait(sb + SM_MBAR(4 + f), phf[f]);
            phf[f] ^= 1;
            if (elect1()) {
                // A desc footprint rows 64..127 read junk (next stage) -> only
                // pollutes D rows 64..127, never read out.
                uint64_t ad = mk_desc(sb + SM_A(c & (NST_A - 1)));
                uint64_t bd = mk_desc(sb + SM_BF(f));
#pragma unroll
                for (int s = 0; s < KC / K_PER_MMA; s++)
                    mma_f16_ss(tmem, ad + s * 2, bd + s * 2, MMA_IDESC,
                               (c > 0 || s > 0) ? 1u : 0u);
                asm volatile(
                    "tcgen05.commit.cta_group::1.mbarrier::arrive::one.shared::cluster.b64 [%0];"
                    :: "r"(sb + SM_MBAR(c & 3)) : "memory");
            }
        }
    }

    __syncthreads();   // converge all 9 warps; A region reused as epilogue scratch

    // ---- epilogue: warp0 holds hi rows (m=lid), warp1 holds lo rows
    const float scale = scalep[0];
    float* Ep = (float*)(smem + EP_OFF);     // [32][33]
    float* Ys = (float*)(smem + YS_OFF);     // [32][68]

    for (int s = 0; s < 2; s++) {
        uint32_t d[32];
        if (wid < 2) {
            asm volatile(
                "tcgen05.ld.sync.aligned.32x32b.x32.b32 "
                "{%0,%1,%2,%3,%4,%5,%6,%7,%8,%9,%10,%11,%12,%13,%14,%15,"
                "%16,%17,%18,%19,%20,%21,%22,%23,%24,%25,%26,%27,%28,%29,%30,%31}, [%32];"
                : "=r"(d[0]), "=r"(d[1]), "=r"(d[2]), "=r"(d[3]), "=r"(d[4]), "=r"(d[5]),
                  "=r"(d[6]), "=r"(d[7]), "=r"(d[8]), "=r"(d[9]), "=r"(d[10]), "=r"(d[11]),
                  "=r"(d[12]), "=r"(d[13]), "=r"(d[14]), "=r"(d[15]), "=r"(d[16]), "=r"(d[17]),
                  "=r"(d[18]), "=r"(d[19]), "=r"(d[20]), "=r"(d[21]), "=r"(d[22]), "=r"(d[23]),
                  "=r"(d[24]), "=r"(d[25]), "=r"(d[26]), "=r"(d[27]), "=r"(d[28]), "=r"(d[29]),
                  "=r"(d[30]), "=r"(d[31])
                : "r"(tmem + s * 32));
            asm volatile("tcgen05.wait::ld.sync.aligned;" ::: "memory");
        }
        if (wid == 1) {
#pragma unroll
            for (int cc = 0; cc < 32; cc++) Ep[lid * 33 + cc] = __uint_as_float(d[cc]);
        }
        __syncthreads();
        if (wid == 0) {
#pragma unroll
            for (int cc = 0; cc < 32; cc++) {
                float hi = __uint_as_float(d[cc]);
                float lo = Ep[lid * 33 + cc];
                float b  = bias[o0 + s * 32 + cc];
                Ys[lid * 68 + s * 32 + cc] = fmaf(scale, hi + lo, b);
            }
        }
        __syncthreads();
    }

    // ---- coalesced store: 32 rows x 64 cols (first 256 threads)
    if (t < 256) {
        const int m = t >> 3, q8 = t & 7;
#pragma unroll
        for (int i = 0; i < 2; i++) {
            const int q = q8 + 8 * i;
            float4 v = *(const float4*)(Ys + m * 68 + q * 4);
            *(float4*)(out + (size_t)m * OUT_DIM + o0 + q * 4) = v;
        }
    }

    __syncthreads();
    if (t == 0) {
#pragma unroll
        for (int s = 0; s < 6; s++)
            asm volatile("mbarrier.inval.shared.b64 [%0];" :: "r"(sb + SM_MBAR(s)) : "memory");
    }
    __syncthreads();
    if (wid == 0) {
        asm volatile("tcgen05.dealloc.cta_group::1.sync.aligned.b32 %0, %1;"
                     :: "r"(tmem), "r"(64u));
    }
#endif  // TC_OK
}

extern "C" void kernel_launch(void* const* d_in, const int* in_sizes, int n_in,
                              void* d_out, int out_size)
{
    const float* x     = (const float*)d_in[0];
    const int*   wq    = (const int*)  d_in[1];
    const int*   zero  = (const int*)  d_in[2];
    const float* scale = (const float*)d_in[3];
    const float* bias  = (const float*)d_in[4];
    float*       out   = (float*)d_out;

    cudaFuncSetAttribute(qgemm_tc, cudaFuncAttributeMaxDynamicSharedMemorySize, SMEM_TOTAL);

    xsplit_kernel<<<(MDIM * IN_DIM + 255) / 256, 256>>>(x);
    qgemm_tc<<<OUT_DIM / NTILE, NTHREADS, SMEM_TOTAL>>>(wq, zero, scale, bias, out);
}